// round 9
// baseline (speedup 1.0000x reference)
#include <cuda_runtime.h>
#include <math_constants.h>
#include <mma.h>

using namespace nvcuda;

#define G 16
#define NB 8192
#define THREADS 256

typedef unsigned long long u64;

// ---- packed f32x2 helpers (sm_103a) for the attention phase ----
__device__ __forceinline__ u64 fma2(u64 a, u64 b, u64 c) {
    u64 d;
    asm("fma.rn.f32x2 %0, %1, %2, %3;" : "=l"(d) : "l"(a), "l"(b), "l"(c));
    return d;
}
__device__ __forceinline__ u64 mul2(u64 a, u64 b) {
    u64 d;
    asm("mul.rn.f32x2 %0, %1, %2;" : "=l"(d) : "l"(a), "l"(b));
    return d;
}
__device__ __forceinline__ u64 splat2(float v) {
    u64 d;
    asm("mov.b64 %0, {%1, %1};" : "=l"(d) : "f"(v));
    return d;
}
__device__ __forceinline__ float2 unpack2(u64 v) {
    float2 r;
    asm("mov.b64 {%0, %1}, %2;" : "=f"(r.x), "=f"(r.y) : "l"(v));
    return r;
}

// Wk transposed: [h][c] = Wk[c][h], 256x512 floats (B matrix for kq GEMM)
__device__ float g_WkT[256 * 512];

__global__ void wkT_kernel(const float* __restrict__ Wk) {
    int idx = blockIdx.x * blockDim.x + threadIdx.x;
    if (idx < 512 * 256) {
        int c = idx >> 8;      // 0..511
        int h = idx & 255;     // 0..255
        g_WkT[h * 512 + c] = Wk[idx];
    }
}

// ---- smem layout (floats). Padded ld to dodge 512-stride bank conflicts. ----
// EE  at 0     : [16][260]  (phase2 C; dead after phase3)     4160 f
// X   at 4160  : [16][516]  (phase2 A; dead after phase2)     8256 f
// Q   at 8256  : [16][260]  (phase3 C, over X-hi; dead after phase4)
// KQ  at 0     : [16][516]  (phase4 C over EE+X-lo; becomes wn in phase5)
// C6  at 8256  : [16][260]  (phase6 C, over Q)
#define LDX 516
#define LDE 260
#define EE_OFF 0
#define X_OFF  4160
#define Q_OFF  8256
#define KQ_OFF 0
#define SMEM_FLOATS 12416
#define SMEM_BYTES (SMEM_FLOATS * 4)

// C[16][256-slice] = A[16][K] @ W[K][*] using 3xTF32 (a_hi*b_hi + a_hi*b_lo + a_lo*b_hi).
// A: smem row-major ld=LDA. W: global row-major ld=WLD. C: smem row-major ld=LDC.
// Covers output cols [nbase, nbase+256): warp wid does tiles nbase+wid*16 and nbase+(wid+8)*16.
template<int K, int WLD, int LDA, int LDC>
__device__ __forceinline__ void gemm3x(const float* __restrict__ A,
                                       const float* __restrict__ W,
                                       float* __restrict__ C,
                                       int wid, int nbase)
{
    wmma::fragment<wmma::accumulator, 16, 16, 8, float> c0, c1;
    wmma::fill_fragment(c0, 0.0f);
    wmma::fill_fragment(c1, 0.0f);
    const int n0 = nbase + wid * 16;
    const int n1 = nbase + (wid + 8) * 16;
    #pragma unroll 1
    for (int k0 = 0; k0 < K; k0 += 8) {
        wmma::fragment<wmma::matrix_a, 16, 16, 8, wmma::precision::tf32, wmma::row_major> ar, ah, al;
        wmma::load_matrix_sync(ar, A + k0, LDA);
        #pragma unroll
        for (int i = 0; i < ar.num_elements; i++) {
            float hi = wmma::__float_to_tf32(ar.x[i]);
            ah.x[i] = hi;
            al.x[i] = wmma::__float_to_tf32(ar.x[i] - hi);
        }
        wmma::fragment<wmma::matrix_b, 16, 16, 8, wmma::precision::tf32, wmma::row_major> br, bh, bl;

        wmma::load_matrix_sync(br, W + (size_t)k0 * WLD + n0, WLD);
        #pragma unroll
        for (int i = 0; i < br.num_elements; i++) {
            float hi = wmma::__float_to_tf32(br.x[i]);
            bh.x[i] = hi;
            bl.x[i] = wmma::__float_to_tf32(br.x[i] - hi);
        }
        wmma::mma_sync(c0, ah, bh, c0);
        wmma::mma_sync(c0, ah, bl, c0);
        wmma::mma_sync(c0, al, bh, c0);

        wmma::load_matrix_sync(br, W + (size_t)k0 * WLD + n1, WLD);
        #pragma unroll
        for (int i = 0; i < br.num_elements; i++) {
            float hi = wmma::__float_to_tf32(br.x[i]);
            bh.x[i] = hi;
            bl.x[i] = wmma::__float_to_tf32(br.x[i] - hi);
        }
        wmma::mma_sync(c1, ah, bh, c1);
        wmma::mma_sync(c1, ah, bl, c1);
        wmma::mma_sync(c1, al, bh, c1);
    }
    wmma::store_matrix_sync(C + n0, c0, LDC, wmma::mem_row_major);
    wmma::store_matrix_sync(C + n1, c1, LDC, wmma::mem_row_major);
}

// 32 neighbors: online softmax, packed f32x2, kq register-resident (R6 form).
__device__ __forceinline__ void attn_seg32(
    const float* __restrict__ relb, const float* __restrict__ nodeb,
    const u64 kqp[8],
    int lane, float& m, float& ssum, u64 waccp[8])
{
    const float* pr = relb + 4 * lane;
    const float* pn = nodeb + 4 * lane;
    #pragma unroll 1
    for (int n = 0; n < 32; n++) {
        ulonglong2 A0 = *(const ulonglong2*)(pr + n * 256);
        ulonglong2 A1 = *(const ulonglong2*)(pr + n * 256 + 128);
        ulonglong2 A2 = *(const ulonglong2*)(pn + n * 256);
        ulonglong2 A3 = *(const ulonglong2*)(pn + n * 256 + 128);

        u64 pp = mul2(A0.x, kqp[0]);
        pp = fma2(A0.y, kqp[1], pp);
        pp = fma2(A1.x, kqp[2], pp);
        pp = fma2(A1.y, kqp[3], pp);
        pp = fma2(A2.x, kqp[4], pp);
        pp = fma2(A2.y, kqp[5], pp);
        pp = fma2(A3.x, kqp[6], pp);
        pp = fma2(A3.y, kqp[7], pp);
        float2 pu = unpack2(pp);
        float p = pu.x + pu.y;
        #pragma unroll
        for (int o = 16; o; o >>= 1) p += __shfl_xor_sync(0xffffffffu, p, o);

        float sn = p * 0.0625f;              // / sqrt(256); q.bk shift cancels in softmax
        if (sn > m) {                        // warp-uniform branch
            float sc = __expf(m - sn);
            ssum *= sc;
            u64 scp = splat2(sc);
            #pragma unroll
            for (int j = 0; j < 8; j++) waccp[j] = mul2(waccp[j], scp);
            m = sn;
        }
        float e = __expf(sn - m);
        ssum += e;
        u64 ep = splat2(e);
        waccp[0] = fma2(ep, A0.x, waccp[0]);
        waccp[1] = fma2(ep, A0.y, waccp[1]);
        waccp[2] = fma2(ep, A1.x, waccp[2]);
        waccp[3] = fma2(ep, A1.y, waccp[3]);
        waccp[4] = fma2(ep, A2.x, waccp[4]);
        waccp[5] = fma2(ep, A2.y, waccp[5]);
        waccp[6] = fma2(ep, A3.x, waccp[6]);
        waccp[7] = fma2(ep, A3.y, waccp[7]);
    }
}

__global__ __launch_bounds__(256, 4)
void superedge_kernel(
    const float* __restrict__ mnode0, const float* __restrict__ mnode1,
    const float* __restrict__ dnode0, const float* __restrict__ dnode1,
    const float* __restrict__ mrel0,  const float* __restrict__ drel0,
    const float* __restrict__ W_edge, const float* __restrict__ b_edge,
    const float* __restrict__ Wq,     const float* __restrict__ bq,
    const float* __restrict__ bk,
    const float* __restrict__ Wv,     const float* __restrict__ bv,
    float* __restrict__ out)
{
    extern __shared__ float smem[];
    float* EE = smem + EE_OFF;
    float* X  = smem + X_OFF;
    float* Q  = smem + Q_OFF;
    float* KQ = smem + KQ_OFF;   // becomes wn in phase 5
    float* C6 = smem + Q_OFF;    // phase6 output (q dead)

    const int tid = threadIdx.x;
    const int b0 = blockIdx.x * G;
    const int wid = tid >> 5, lane = tid & 31;

    // ---------------- Phase 1: X[g][0:512] = [mnode0_b | dnode0_b]
    #pragma unroll
    for (int g = 0; g < G; g++) {
        int b = b0 + g;
        X[g * LDX + tid]       = mnode0[(size_t)b * 256 + tid];
        X[g * LDX + 256 + tid] = dnode0[(size_t)b * 256 + tid];
    }
    __syncthreads();

    // ---------------- Phase 2: EE = relu(X @ W_edge + b_edge)
    gemm3x<512, 256, LDX, LDE>(X, W_edge, EE, wid, 0);
    __syncthreads();
    {
        float bias = b_edge[tid];
        #pragma unroll
        for (int g = 0; g < G; g++) {
            float v = fmaxf(EE[g * LDE + tid] + bias, 0.0f);
            EE[g * LDE + tid] = v;
            out[(size_t)(b0 + g) * 512 + tid] = v;     // first half of output
        }
    }
    __syncthreads();

    // ---------------- Phase 3: Q = EE @ Wq + bq
    gemm3x<256, 256, LDE, LDE>(EE, Wq, Q, wid, 0);
    __syncthreads();
    {
        float bias = bq[tid];
        #pragma unroll
        for (int g = 0; g < G; g++) Q[g * LDE + tid] += bias;
    }
    __syncthreads();

    // ---------------- Phase 4: KQ = Q @ WkT   (bk shift cancels in softmax)
    gemm3x<256, 512, LDE, LDX>(Q, g_WkT, KQ, wid, 0);
    gemm3x<256, 512, LDE, LDX>(Q, g_WkT, KQ, wid, 256);
    __syncthreads();

    // ---------------- Phase 5: warp wid owns batches 2wid, 2wid+1; wn over own kq row
    #pragma unroll 1
    for (int gi = 0; gi < 2; gi++) {
        const int g = 2 * wid + gi;
        const int b = b0 + g;
        float* kqg = KQ + g * LDX;

        u64 kqr[8];
        {
            ulonglong2 k0 = *(const ulonglong2*)&kqg[4 * lane];
            ulonglong2 k1 = *(const ulonglong2*)&kqg[128 + 4 * lane];
            ulonglong2 k2 = *(const ulonglong2*)&kqg[256 + 4 * lane];
            ulonglong2 k3 = *(const ulonglong2*)&kqg[384 + 4 * lane];
            kqr[0] = k0.x; kqr[1] = k0.y;
            kqr[2] = k1.x; kqr[3] = k1.y;
            kqr[4] = k2.x; kqr[5] = k2.y;
            kqr[6] = k3.x; kqr[7] = k3.y;
        }

        float m = -CUDART_INF_F, ssum = 0.0f;
        u64 waccp[8];
        #pragma unroll
        for (int j = 0; j < 8; j++) waccp[j] = splat2(0.0f);

        attn_seg32(mrel0 + (size_t)b * 32 * 256, mnode1 + (size_t)b * 32 * 256,
                   kqr, lane, m, ssum, waccp);
        attn_seg32(drel0 + (size_t)b * 32 * 256, dnode1 + (size_t)b * 32 * 256,
                   kqr, lane, m, ssum, waccp);

        u64 invp = splat2(1.0f / ssum);
        // wn[g][c], c = ch*128 + 4*lane + 2k(+1), in place over this warp's kq row
        #pragma unroll
        for (int ch = 0; ch < 4; ch++) {
            #pragma unroll
            for (int k = 0; k < 2; k++) {
                u64 v = mul2(waccp[ch * 2 + k], invp);
                *(u64*)&kqg[ch * 128 + 4 * lane + 2 * k] = v;
            }
        }
    }
    __syncthreads();

    // ---------------- Phase 6: C6 = wn @ Wv; out2 = C6 + bv
    gemm3x<512, 256, LDX, LDE>(KQ, Wv, C6, wid, 0);
    __syncthreads();
    {
        float bias = bv[tid];
        #pragma unroll
        for (int g = 0; g < G; g++)
            out[(size_t)(b0 + g) * 512 + 256 + tid] = C6[g * LDE + tid] + bias;
    }
}

extern "C" void kernel_launch(void* const* d_in, const int* in_sizes, int n_in,
                              void* d_out, int out_size) {
    const float* mnode0 = (const float*)d_in[0];
    const float* mnode1 = (const float*)d_in[1];
    const float* dnode0 = (const float*)d_in[2];
    const float* dnode1 = (const float*)d_in[3];
    const float* mrel0  = (const float*)d_in[4];
    const float* drel0  = (const float*)d_in[5];
    const float* W_edge = (const float*)d_in[6];
    const float* b_edge = (const float*)d_in[7];
    const float* Wq     = (const float*)d_in[8];
    const float* bq     = (const float*)d_in[9];
    const float* Wk     = (const float*)d_in[10];
    const float* bk     = (const float*)d_in[11];
    const float* Wv     = (const float*)d_in[12];
    const float* bv     = (const float*)d_in[13];
    float* out = (float*)d_out;

    cudaFuncSetAttribute(superedge_kernel,
                         cudaFuncAttributeMaxDynamicSharedMemorySize, SMEM_BYTES);

    wkT_kernel<<<512, 256>>>(Wk);
    superedge_kernel<<<NB / G, THREADS, SMEM_BYTES>>>(
        mnode0, mnode1, dnode0, dnode1, mrel0, drel0,
        W_edge, b_edge, Wq, bq, bk, Wv, bv, out);
}

// round 10
// speedup vs baseline: 1.0080x; 1.0080x over previous
#include <cuda_runtime.h>
#include <math_constants.h>
#include <mma.h>

using namespace nvcuda;

#define NB 8192
typedef unsigned long long u64;

// ---------------- device scratch ----------------
__device__ float g_WkT[256 * 512];   // Wk transposed [h][c]
__device__ float g_EE[NB * 256];
__device__ float g_Q [NB * 256];
__device__ float g_KQ[NB * 512];
__device__ float g_WN[NB * 512];

__global__ void wkT_kernel(const float* __restrict__ Wk) {
    int idx = blockIdx.x * blockDim.x + threadIdx.x;
    if (idx < 512 * 256) {
        int c = idx >> 8;
        int h = idx & 255;
        g_WkT[h * 512 + c] = Wk[idx];
    }
}

// ---- packed f32x2 helpers (attention) ----
__device__ __forceinline__ u64 fma2(u64 a, u64 b, u64 c) {
    u64 d; asm("fma.rn.f32x2 %0, %1, %2, %3;" : "=l"(d) : "l"(a), "l"(b), "l"(c)); return d;
}
__device__ __forceinline__ u64 mul2(u64 a, u64 b) {
    u64 d; asm("mul.rn.f32x2 %0, %1, %2;" : "=l"(d) : "l"(a), "l"(b)); return d;
}
__device__ __forceinline__ u64 splat2(float v) {
    u64 d; asm("mov.b64 %0, {%1, %1};" : "=l"(d) : "f"(v)); return d;
}
__device__ __forceinline__ float2 unpack2(u64 v) {
    float2 r; asm("mov.b64 {%0, %1}, %2;" : "=f"(r.x), "=f"(r.y) : "l"(v)); return r;
}

// ---- tf32 3x split helper ----
template<typename F>
__device__ __forceinline__ void split3(const F& r, F& h, F& l) {
    #pragma unroll
    for (int i = 0; i < r.num_elements; i++) {
        float hi = wmma::__float_to_tf32(r.x[i]);
        h.x[i] = hi;
        l.x[i] = wmma::__float_to_tf32(r.x[i] - hi);
    }
}

// ================= tiled tf32-3x GEMM =================
// C[128-tile, 64-tile] = A[M,K] @ W[K,NG]; 256 threads, warp-tile 32x32.
// SA: 0 = concat(Aext0,Aext1) (K=512, halves of 256); 1 = g_EE; 2 = g_Q; 3 = g_WN
// SW: 0 = Wext; 1 = g_WkT
// SC: 0 = Cext (ldc, coloff); 1 = g_Q; 2 = g_KQ
template<int SA, int SW, int SC, bool HAS_BIAS, bool DO_RELU, bool DUAL, int K, int NG>
__global__ __launch_bounds__(256)
void gemm_k(const float* __restrict__ Aext0, const float* __restrict__ Aext1,
            const float* __restrict__ Wext,  const float* __restrict__ biasp,
            float* __restrict__ Cext, int ldc, int coloff)
{
    __shared__ union {
        struct { float As[128 * 36]; float Bs[32 * 68]; } s;
        float Cs[128 * 72];
    } sm;

    const int tid = threadIdx.x;
    const int wid = tid >> 5;
    const int wr = wid >> 1, wc = wid & 1;          // 4x2 warp grid
    const int mb = blockIdx.x * 128, nb = blockIdx.y * 64;

    const float* W = (SW == 0) ? Wext : (const float*)g_WkT;

    wmma::fragment<wmma::accumulator, 16, 16, 8, float> c[2][2];
    #pragma unroll
    for (int i = 0; i < 2; i++)
        #pragma unroll
        for (int j = 0; j < 2; j++)
            wmma::fill_fragment(c[i][j], 0.0f);

    #pragma unroll 1
    for (int k0 = 0; k0 < K; k0 += 32) {
        // stage A chunk [128][32]
        {
            int row = tid >> 1;
            int off = (tid & 1) * 16;
            const float* src;
            if (SA == 0) {
                const float* base = (k0 < 256) ? Aext0 : Aext1;
                int kk = (k0 < 256) ? k0 : k0 - 256;
                src = base + (size_t)(mb + row) * 256 + kk + off;
            } else {
                const float* base = (SA == 1) ? g_EE : (SA == 2) ? g_Q : g_WN;
                src = base + (size_t)(mb + row) * K + k0 + off;
            }
            float* dst = &sm.s.As[row * 36 + off];
            #pragma unroll
            for (int j = 0; j < 4; j++)
                *(float4*)(dst + j * 4) = *(const float4*)(src + j * 4);
        }
        // stage B chunk [32][64]
        {
            int row = tid >> 3;
            int cseg = (tid & 7) * 8;
            const float* src = W + (size_t)(k0 + row) * NG + nb + cseg;
            float* dst = &sm.s.Bs[row * 68 + cseg];
            *(float4*)dst = *(const float4*)src;
            *(float4*)(dst + 4) = *(const float4*)(src + 4);
        }
        __syncthreads();

        #pragma unroll
        for (int ks = 0; ks < 4; ks++) {
            int kk = ks * 8;
            wmma::fragment<wmma::matrix_b, 16, 16, 8, wmma::precision::tf32, wmma::row_major> bh[2], bl[2];
            #pragma unroll
            for (int j = 0; j < 2; j++) {
                wmma::fragment<wmma::matrix_b, 16, 16, 8, wmma::precision::tf32, wmma::row_major> br;
                wmma::load_matrix_sync(br, &sm.s.Bs[kk * 68 + wc * 32 + j * 16], 68);
                split3(br, bh[j], bl[j]);
            }
            #pragma unroll
            for (int i = 0; i < 2; i++) {
                wmma::fragment<wmma::matrix_a, 16, 16, 8, wmma::precision::tf32, wmma::row_major> ar, ah, al;
                wmma::load_matrix_sync(ar, &sm.s.As[(wr * 32 + i * 16) * 36 + kk], 36);
                split3(ar, ah, al);
                #pragma unroll
                for (int j = 0; j < 2; j++) {
                    wmma::mma_sync(c[i][j], ah, bh[j], c[i][j]);
                    wmma::mma_sync(c[i][j], ah, bl[j], c[i][j]);
                    wmma::mma_sync(c[i][j], al, bh[j], c[i][j]);
                }
            }
        }
        __syncthreads();
    }

    // epilogue through smem
    #pragma unroll
    for (int i = 0; i < 2; i++)
        #pragma unroll
        for (int j = 0; j < 2; j++)
            wmma::store_matrix_sync(&sm.Cs[(wr * 32 + i * 16) * 72 + wc * 32 + j * 16],
                                    c[i][j], 72, wmma::mem_row_major);
    __syncthreads();

    #pragma unroll
    for (int i = 0; i < 8; i++) {
        int id = tid + i * 256;
        int row = id >> 4;
        int col = (id & 15) << 2;
        float4 v = *(float4*)&sm.Cs[row * 72 + col];
        if (HAS_BIAS) {
            float4 b4 = *(const float4*)&biasp[nb + col];
            v.x += b4.x; v.y += b4.y; v.z += b4.z; v.w += b4.w;
        }
        if (DO_RELU) {
            v.x = fmaxf(v.x, 0.0f); v.y = fmaxf(v.y, 0.0f);
            v.z = fmaxf(v.z, 0.0f); v.w = fmaxf(v.w, 0.0f);
        }
        float* cb;
        if (SC == 0)      cb = Cext + (size_t)(mb + row) * ldc + coloff + nb + col;
        else if (SC == 1) cb = g_Q  + (size_t)(mb + row) * 256 + nb + col;
        else              cb = g_KQ + (size_t)(mb + row) * 512 + nb + col;
        *(float4*)cb = v;
        if (DUAL)
            *(float4*)&g_EE[(size_t)(mb + row) * 256 + nb + col] = v;
    }
}

// ================= attention (R6 phase-5 standalone) =================
__device__ __forceinline__ void attn_seg32(
    const float* __restrict__ relb, const float* __restrict__ nodeb,
    const u64 kqp[8],
    int lane, float& m, float& ssum, u64 waccp[8])
{
    const float* pr = relb + 4 * lane;
    const float* pn = nodeb + 4 * lane;
    #pragma unroll 1
    for (int n = 0; n < 32; n++) {
        ulonglong2 A0 = *(const ulonglong2*)(pr + n * 256);
        ulonglong2 A1 = *(const ulonglong2*)(pr + n * 256 + 128);
        ulonglong2 A2 = *(const ulonglong2*)(pn + n * 256);
        ulonglong2 A3 = *(const ulonglong2*)(pn + n * 256 + 128);

        u64 pp = mul2(A0.x, kqp[0]);
        pp = fma2(A0.y, kqp[1], pp);
        pp = fma2(A1.x, kqp[2], pp);
        pp = fma2(A1.y, kqp[3], pp);
        pp = fma2(A2.x, kqp[4], pp);
        pp = fma2(A2.y, kqp[5], pp);
        pp = fma2(A3.x, kqp[6], pp);
        pp = fma2(A3.y, kqp[7], pp);
        float2 pu = unpack2(pp);
        float p = pu.x + pu.y;
        #pragma unroll
        for (int o = 16; o; o >>= 1) p += __shfl_xor_sync(0xffffffffu, p, o);

        float sn = p * 0.0625f;              // /sqrt(256); q.bk shift cancels in softmax
        if (sn > m) {
            float sc = __expf(m - sn);
            ssum *= sc;
            u64 scp = splat2(sc);
            #pragma unroll
            for (int j = 0; j < 8; j++) waccp[j] = mul2(waccp[j], scp);
            m = sn;
        }
        float e = __expf(sn - m);
        ssum += e;
        u64 ep = splat2(e);
        waccp[0] = fma2(ep, A0.x, waccp[0]);
        waccp[1] = fma2(ep, A0.y, waccp[1]);
        waccp[2] = fma2(ep, A1.x, waccp[2]);
        waccp[3] = fma2(ep, A1.y, waccp[3]);
        waccp[4] = fma2(ep, A2.x, waccp[4]);
        waccp[5] = fma2(ep, A2.y, waccp[5]);
        waccp[6] = fma2(ep, A3.x, waccp[6]);
        waccp[7] = fma2(ep, A3.y, waccp[7]);
    }
}

__global__ __launch_bounds__(256)
void attn_kernel(const float* __restrict__ mrel0, const float* __restrict__ mnode1,
                 const float* __restrict__ drel0, const float* __restrict__ dnode1)
{
    const int wid = threadIdx.x >> 5, lane = threadIdx.x & 31;
    const int b = blockIdx.x * 8 + wid;

    const float* kqg = g_KQ + (size_t)b * 512;
    u64 kqr[8];
    {
        ulonglong2 k0 = *(const ulonglong2*)(kqg + 4 * lane);
        ulonglong2 k1 = *(const ulonglong2*)(kqg + 128 + 4 * lane);
        ulonglong2 k2 = *(const ulonglong2*)(kqg + 256 + 4 * lane);
        ulonglong2 k3 = *(const ulonglong2*)(kqg + 384 + 4 * lane);
        kqr[0] = k0.x; kqr[1] = k0.y;
        kqr[2] = k1.x; kqr[3] = k1.y;
        kqr[4] = k2.x; kqr[5] = k2.y;
        kqr[6] = k3.x; kqr[7] = k3.y;
    }

    float m = -CUDART_INF_F, ssum = 0.0f;
    u64 waccp[8];
    #pragma unroll
    for (int j = 0; j < 8; j++) waccp[j] = splat2(0.0f);

    attn_seg32(mrel0 + (size_t)b * 32 * 256, mnode1 + (size_t)b * 32 * 256,
               kqr, lane, m, ssum, waccp);
    attn_seg32(drel0 + (size_t)b * 32 * 256, dnode1 + (size_t)b * 32 * 256,
               kqr, lane, m, ssum, waccp);

    u64 invp = splat2(1.0f / ssum);
    float* wn = g_WN + (size_t)b * 512;
    #pragma unroll
    for (int ch = 0; ch < 4; ch++) {
        #pragma unroll
        for (int k = 0; k < 2; k++) {
            u64 v = mul2(waccp[ch * 2 + k], invp);
            *(u64*)(wn + ch * 128 + 4 * lane + 2 * k) = v;
        }
    }
}

// ================= launch =================
extern "C" void kernel_launch(void* const* d_in, const int* in_sizes, int n_in,
                              void* d_out, int out_size) {
    const float* mnode0 = (const float*)d_in[0];
    const float* mnode1 = (const float*)d_in[1];
    const float* dnode0 = (const float*)d_in[2];
    const float* dnode1 = (const float*)d_in[3];
    const float* mrel0  = (const float*)d_in[4];
    const float* drel0  = (const float*)d_in[5];
    const float* W_edge = (const float*)d_in[6];
    const float* b_edge = (const float*)d_in[7];
    const float* Wq     = (const float*)d_in[8];
    const float* bq     = (const float*)d_in[9];
    const float* Wk     = (const float*)d_in[10];
    const float* bk     = (const float*)d_in[11];   // cancels in softmax
    const float* Wv     = (const float*)d_in[12];
    const float* bv     = (const float*)d_in[13];
    float* out = (float*)d_out;
    (void)bk;

    wkT_kernel<<<512, 256>>>(Wk);

    // EE = relu(concat(mnode0,dnode0) @ W_edge + b_edge) -> out[:, :256] and g_EE
    gemm_k<0, 0, 0, true, true, true, 512, 256>
        <<<dim3(64, 4), 256>>>(mnode0, dnode0, W_edge, b_edge, out, 512, 0);

    // Q = EE @ Wq + bq -> g_Q
    gemm_k<1, 0, 1, true, false, false, 256, 256>
        <<<dim3(64, 4), 256>>>(nullptr, nullptr, Wq, bq, nullptr, 0, 0);

    // KQ = Q @ WkT -> g_KQ
    gemm_k<2, 1, 2, false, false, false, 256, 512>
        <<<dim3(64, 8), 256>>>(nullptr, nullptr, nullptr, nullptr, nullptr, 0, 0);

    // attention: WN = softmax(edge_nei @ KQ / 16) weighted sum -> g_WN
    attn_kernel<<<NB / 8, 256>>>(mrel0, mnode1, drel0, dnode1);

    // out[:, 256:] = WN @ Wv + bv
    gemm_k<3, 0, 0, true, false, false, 512, 256>
        <<<dim3(64, 4), 256>>>(nullptr, nullptr, Wv, bv, out, 512, 256);
}

// round 12
// speedup vs baseline: 1.0924x; 1.0837x over previous
#include <cstdint>
#include <cuda_runtime.h>
#include <math_constants.h>
#include <mma.h>

using namespace nvcuda;

#define NB 8192
typedef unsigned long long u64;

// ---------------- device scratch ----------------
__device__ float g_WkT[256 * 512];   // Wk transposed [h][c]
__device__ float g_Wqk[256 * 512];   // Wq @ WkT
__device__ float g_bqk[512];         // bq @ WkT
__device__ float g_EE[NB * 256];
__device__ float g_KQ[(size_t)NB * 512];
__device__ float g_WN[(size_t)NB * 512];

__global__ void wkT_kernel(const float* __restrict__ Wk) {
    int idx = blockIdx.x * blockDim.x + threadIdx.x;
    if (idx < 512 * 256) {
        int c = idx >> 8;
        int h = idx & 255;
        g_WkT[h * 512 + c] = Wk[idx];
    }
}

// Wqk[e][c] = sum_h Wq[e][h] * WkT[h][c]   (fp32, L2-hot)
__global__ void wqk_kernel(const float* __restrict__ Wq) {
    int idx = blockIdx.x * 256 + threadIdx.x;   // 131072 threads
    int e = idx >> 9, c = idx & 511;
    const float* wq = Wq + e * 256;
    float s = 0.0f;
    #pragma unroll 8
    for (int h = 0; h < 256; h++) s += wq[h] * g_WkT[h * 512 + c];
    g_Wqk[e * 512 + c] = s;
}

// bqk[c] = sum_h bq[h] * WkT[h][c]
__global__ void bqk_kernel(const float* __restrict__ bq) {
    int c = blockIdx.x * 256 + threadIdx.x;
    float s = 0.0f;
    #pragma unroll 8
    for (int h = 0; h < 256; h++) s += bq[h] * g_WkT[h * 512 + c];
    g_bqk[c] = s;
}

// ---- packed f32x2 helpers (attention) ----
__device__ __forceinline__ u64 fma2(u64 a, u64 b, u64 c) {
    u64 d; asm("fma.rn.f32x2 %0, %1, %2, %3;" : "=l"(d) : "l"(a), "l"(b), "l"(c)); return d;
}
__device__ __forceinline__ u64 mul2(u64 a, u64 b) {
    u64 d; asm("mul.rn.f32x2 %0, %1, %2;" : "=l"(d) : "l"(a), "l"(b)); return d;
}
__device__ __forceinline__ u64 splat2(float v) {
    u64 d; asm("mov.b64 %0, {%1, %1};" : "=l"(d) : "f"(v)); return d;
}
__device__ __forceinline__ float2 unpack2(u64 v) {
    float2 r; asm("mov.b64 {%0, %1}, %2;" : "=f"(r.x), "=f"(r.y) : "l"(v)); return r;
}

// ---- cp.async ----
__device__ __forceinline__ void cpa16(uint32_t dst, const float* src) {
    asm volatile("cp.async.ca.shared.global [%0], [%1], 16;" :: "r"(dst), "l"(src));
}
#define CPA_COMMIT() asm volatile("cp.async.commit_group;")
#define CPA_WAIT0()  asm volatile("cp.async.wait_group 0;")

// ---- tf32 3x split helper ----
template<typename F>
__device__ __forceinline__ void split3(const F& r, F& h, F& l) {
    #pragma unroll
    for (int i = 0; i < r.num_elements; i++) {
        float hi = wmma::__float_to_tf32(r.x[i]);
        h.x[i] = hi;
        l.x[i] = wmma::__float_to_tf32(r.x[i] - hi);
    }
}

// ================= cp.async double-buffered tf32-3x GEMM =================
// C[128, 64-tile] = A[M,K] @ W[K,NG]; 256 threads, 4x2 warp grid, warp-tile 32x32.
// SA: 0 = concat(Aext0,Aext1); 1 = g_EE; 3 = g_WN
// SW: 0 = Wext; 1 = g_Wqk
// SC: 0 = Cext (ldc,coloff); 2 = g_KQ
// Dyn smem: As[2][128*36] (9216 f) + Bs[2][32*68] (4352 f) = 54272 B; Cs overlays.
#define GEMM_SMEM_BYTES ((9216 + 4352) * 4)

template<int SA, int SW, int SC, bool HAS_BIAS, bool DO_RELU, bool DUAL, int K, int NG>
__global__ __launch_bounds__(256)
void gemm_k(const float* __restrict__ Aext0, const float* __restrict__ Aext1,
            const float* __restrict__ Wext,  const float* __restrict__ biasp,
            float* __restrict__ Cext, int ldc, int coloff)
{
    extern __shared__ float sm[];
    float* As = sm;               // [2][128*36]
    float* Bs = sm + 9216;        // [2][32*68]
    float* Cs = sm;               // epilogue overlay [128*72]

    const int tid = threadIdx.x;
    const int wid = tid >> 5;
    const int wr = wid >> 1, wc = wid & 1;
    const int mb = blockIdx.x * 128, nb = blockIdx.y * 64;

    const float* W = (SW == 0) ? Wext : (const float*)g_Wqk;
    const uint32_t as_base = (uint32_t)__cvta_generic_to_shared(As);
    const uint32_t bs_base = (uint32_t)__cvta_generic_to_shared(Bs);

    // staging geometry
    const int arow = tid >> 1, aoff = (tid & 1) * 16;
    const int brow = tid >> 3, bseg = (tid & 7) * 8;

    auto stage = [&](int bb, int k0) {
        const float* asrc;
        if (SA == 0) {
            const float* base = (k0 < 256) ? Aext0 : Aext1;
            int kk = (k0 < 256) ? k0 : k0 - 256;
            asrc = base + (size_t)(mb + arow) * 256 + kk + aoff;
        } else {
            const float* base = (SA == 1) ? g_EE : g_WN;
            asrc = base + (size_t)(mb + arow) * K + k0 + aoff;
        }
        uint32_t ad = as_base + (uint32_t)(bb * 4608 + arow * 36 + aoff) * 4u;
        #pragma unroll
        for (int j = 0; j < 4; j++) cpa16(ad + j * 16, asrc + j * 4);

        const float* bsrc = W + (size_t)(k0 + brow) * NG + nb + bseg;
        uint32_t bd = bs_base + (uint32_t)(bb * 2176 + brow * 68 + bseg) * 4u;
        cpa16(bd, bsrc);
        cpa16(bd + 16, bsrc + 4);
        CPA_COMMIT();
    };

    wmma::fragment<wmma::accumulator, 16, 16, 8, float> c[2][2];
    #pragma unroll
    for (int i = 0; i < 2; i++)
        #pragma unroll
        for (int j = 0; j < 2; j++)
            wmma::fill_fragment(c[i][j], 0.0f);

    stage(0, 0);
    CPA_WAIT0();
    __syncthreads();

    #pragma unroll 1
    for (int k0 = 0; k0 < K; k0 += 32) {
        const int cur = (k0 >> 5) & 1;
        if (k0 + 32 < K) stage(cur ^ 1, k0 + 32);   // async; overlaps compute below

        const float* Asb = As + cur * 4608;
        const float* Bsb = Bs + cur * 2176;
        #pragma unroll
        for (int ks = 0; ks < 4; ks++) {
            int kk = ks * 8;
            wmma::fragment<wmma::matrix_b, 16, 16, 8, wmma::precision::tf32, wmma::row_major> bh[2], bl[2];
            #pragma unroll
            for (int j = 0; j < 2; j++) {
                wmma::fragment<wmma::matrix_b, 16, 16, 8, wmma::precision::tf32, wmma::row_major> br;
                wmma::load_matrix_sync(br, Bsb + kk * 68 + wc * 32 + j * 16, 68);
                split3(br, bh[j], bl[j]);
            }
            #pragma unroll
            for (int i = 0; i < 2; i++) {
                wmma::fragment<wmma::matrix_a, 16, 16, 8, wmma::precision::tf32, wmma::row_major> ar, ah, al;
                wmma::load_matrix_sync(ar, Asb + (wr * 32 + i * 16) * 36 + kk, 36);
                split3(ar, ah, al);
                #pragma unroll
                for (int j = 0; j < 2; j++) {
                    wmma::mma_sync(c[i][j], ah, bh[j], c[i][j]);
                    wmma::mma_sync(c[i][j], ah, bl[j], c[i][j]);
                    wmma::mma_sync(c[i][j], al, bh[j], c[i][j]);
                }
            }
        }
        CPA_WAIT0();
        __syncthreads();
    }

    // epilogue through smem (overlays As/Bs — all compute done)
    #pragma unroll
    for (int i = 0; i < 2; i++)
        #pragma unroll
        for (int j = 0; j < 2; j++)
            wmma::store_matrix_sync(Cs + (wr * 32 + i * 16) * 72 + wc * 32 + j * 16,
                                    c[i][j], 72, wmma::mem_row_major);
    __syncthreads();

    const float* bias = HAS_BIAS ? ((biasp != nullptr) ? biasp : (const float*)g_bqk) : nullptr;
    #pragma unroll
    for (int i = 0; i < 8; i++) {
        int id = tid + i * 256;
        int row = id >> 4;
        int col = (id & 15) << 2;
        float4 v = *(float4*)&Cs[row * 72 + col];
        if (HAS_BIAS) {
            float4 b4 = *(const float4*)&bias[nb + col];
            v.x += b4.x; v.y += b4.y; v.z += b4.z; v.w += b4.w;
        }
        if (DO_RELU) {
            v.x = fmaxf(v.x, 0.0f); v.y = fmaxf(v.y, 0.0f);
            v.z = fmaxf(v.z, 0.0f); v.w = fmaxf(v.w, 0.0f);
        }
        float* cb;
        if (SC == 0) cb = Cext + (size_t)(mb + row) * ldc + coloff + nb + col;
        else         cb = g_KQ + (size_t)(mb + row) * 512 + nb + col;
        *(float4*)cb = v;
        if (DUAL)
            *(float4*)&g_EE[(size_t)(mb + row) * 256 + nb + col] = v;
    }
}

// ================= attention: warp/batch, 2 neighbors per iter =================
__device__ __forceinline__ void attn_seg32_x2(
    const float* __restrict__ relb, const float* __restrict__ nodeb,
    const u64 kqp[8],
    int lane, float& m, float& ssum, u64 waccp[8])
{
    const float* pr = relb + 4 * lane;
    const float* pn = nodeb + 4 * lane;
    #pragma unroll 1
    for (int n = 0; n < 32; n += 2) {
        ulonglong2 A0 = *(const ulonglong2*)(pr + n * 256);
        ulonglong2 A1 = *(const ulonglong2*)(pr + n * 256 + 128);
        ulonglong2 A2 = *(const ulonglong2*)(pn + n * 256);
        ulonglong2 A3 = *(const ulonglong2*)(pn + n * 256 + 128);
        ulonglong2 B0 = *(const ulonglong2*)(pr + n * 256 + 256);
        ulonglong2 B1 = *(const ulonglong2*)(pr + n * 256 + 384);
        ulonglong2 B2 = *(const ulonglong2*)(pn + n * 256 + 256);
        ulonglong2 B3 = *(const ulonglong2*)(pn + n * 256 + 384);

        u64 pA = mul2(A0.x, kqp[0]);
        u64 pB = mul2(B0.x, kqp[0]);
        pA = fma2(A0.y, kqp[1], pA);  pB = fma2(B0.y, kqp[1], pB);
        pA = fma2(A1.x, kqp[2], pA);  pB = fma2(B1.x, kqp[2], pB);
        pA = fma2(A1.y, kqp[3], pA);  pB = fma2(B1.y, kqp[3], pB);
        pA = fma2(A2.x, kqp[4], pA);  pB = fma2(B2.x, kqp[4], pB);
        pA = fma2(A2.y, kqp[5], pA);  pB = fma2(B2.y, kqp[5], pB);
        pA = fma2(A3.x, kqp[6], pA);  pB = fma2(B3.x, kqp[6], pB);
        pA = fma2(A3.y, kqp[7], pA);  pB = fma2(B3.y, kqp[7], pB);

        float2 ua = unpack2(pA), ub = unpack2(pB);
        float pa = ua.x + ua.y, pb = ub.x + ub.y;
        #pragma unroll
        for (int o = 16; o; o >>= 1) {
            pa += __shfl_xor_sync(0xffffffffu, pa, o);
            pb += __shfl_xor_sync(0xffffffffu, pb, o);
        }
        float snA = pa * 0.0625f;      // /sqrt(256); q.bk shift cancels in softmax
        float snB = pb * 0.0625f;

        float mn = fmaxf(snA, snB);
        if (mn > m) {                  // warp-uniform
            float sc = __expf(m - mn);
            ssum *= sc;
            u64 scp = splat2(sc);
            #pragma unroll
            for (int j = 0; j < 8; j++) waccp[j] = mul2(waccp[j], scp);
            m = mn;
        }
        float eA = __expf(snA - m);
        float eB = __expf(snB - m);
        ssum += eA + eB;
        u64 eAp = splat2(eA), eBp = splat2(eB);
        waccp[0] = fma2(eAp, A0.x, fma2(eBp, B0.x, waccp[0]));
        waccp[1] = fma2(eAp, A0.y, fma2(eBp, B0.y, waccp[1]));
        waccp[2] = fma2(eAp, A1.x, fma2(eBp, B1.x, waccp[2]));
        waccp[3] = fma2(eAp, A1.y, fma2(eBp, B1.y, waccp[3]));
        waccp[4] = fma2(eAp, A2.x, fma2(eBp, B2.x, waccp[4]));
        waccp[5] = fma2(eAp, A2.y, fma2(eBp, B2.y, waccp[5]));
        waccp[6] = fma2(eAp, A3.x, fma2(eBp, B3.x, waccp[6]));
        waccp[7] = fma2(eAp, A3.y, fma2(eBp, B3.y, waccp[7]));
    }
}

__global__ __launch_bounds__(256, 3)
void attn_kernel(const float* __restrict__ mrel0, const float* __restrict__ mnode1,
                 const float* __restrict__ drel0, const float* __restrict__ dnode1)
{
    const int wid = threadIdx.x >> 5, lane = threadIdx.x & 31;
    const int b = blockIdx.x * 8 + wid;

    const float* kqg = g_KQ + (size_t)b * 512;
    u64 kqr[8];
    {
        ulonglong2 k0 = *(const ulonglong2*)(kqg + 4 * lane);
        ulonglong2 k1 = *(const ulonglong2*)(kqg + 128 + 4 * lane);
        ulonglong2 k2 = *(const ulonglong2*)(kqg + 256 + 4 * lane);
        ulonglong2 k3 = *(const ulonglong2*)(kqg + 384 + 4 * lane);
        kqr[0] = k0.x; kqr[1] = k0.y;
        kqr[2] = k1.x; kqr[3] = k1.y;
        kqr[4] = k2.x; kqr[5] = k2.y;
        kqr[6] = k3.x; kqr[7] = k3.y;
    }

    float m = -CUDART_INF_F, ssum = 0.0f;
    u64 waccp[8];
    #pragma unroll
    for (int j = 0; j < 8; j++) waccp[j] = splat2(0.0f);

    attn_seg32_x2(mrel0 + (size_t)b * 32 * 256, mnode1 + (size_t)b * 32 * 256,
                  kqr, lane, m, ssum, waccp);
    attn_seg32_x2(drel0 + (size_t)b * 32 * 256, dnode1 + (size_t)b * 32 * 256,
                  kqr, lane, m, ssum, waccp);

    u64 invp = splat2(1.0f / ssum);
    float* wn = g_WN + (size_t)b * 512;
    #pragma unroll
    for (int ch = 0; ch < 4; ch++) {
        #pragma unroll
        for (int k = 0; k < 2; k++) {
            u64 v = mul2(waccp[ch * 2 + k], invp);
            *(u64*)(wn + ch * 128 + 4 * lane + 2 * k) = v;
        }
    }
}

// ================= launch =================
extern "C" void kernel_launch(void* const* d_in, const int* in_sizes, int n_in,
                              void* d_out, int out_size) {
    const float* mnode0 = (const float*)d_in[0];
    const float* mnode1 = (const float*)d_in[1];
    const float* dnode0 = (const float*)d_in[2];
    const float* dnode1 = (const float*)d_in[3];
    const float* mrel0  = (const float*)d_in[4];
    const float* drel0  = (const float*)d_in[5];
    const float* W_edge = (const float*)d_in[6];
    const float* b_edge = (const float*)d_in[7];
    const float* Wq     = (const float*)d_in[8];
    const float* bq     = (const float*)d_in[9];
    const float* Wk     = (const float*)d_in[10];
    const float* bk     = (const float*)d_in[11];   // cancels in softmax
    const float* Wv     = (const float*)d_in[12];
    const float* bv     = (const float*)d_in[13];
    float* out = (float*)d_out;
    (void)bk;

    cudaFuncSetAttribute((const void*)gemm_k<0,0,0,true,true,true,512,256>,
                         cudaFuncAttributeMaxDynamicSharedMemorySize, GEMM_SMEM_BYTES);
    cudaFuncSetAttribute((const void*)gemm_k<1,1,2,true,false,false,256,512>,
                         cudaFuncAttributeMaxDynamicSharedMemorySize, GEMM_SMEM_BYTES);
    cudaFuncSetAttribute((const void*)gemm_k<3,0,0,true,false,false,512,256>,
                         cudaFuncAttributeMaxDynamicSharedMemorySize, GEMM_SMEM_BYTES);

    wkT_kernel<<<512, 256>>>(Wk);
    wqk_kernel<<<512, 256>>>(Wq);
    bqk_kernel<<<2, 256>>>(bq);

    // EE = relu(concat(mnode0,dnode0) @ W_edge + b_edge) -> out[:, :256] and g_EE
    gemm_k<0, 0, 0, true, true, true, 512, 256>
        <<<dim3(64, 4), 256, GEMM_SMEM_BYTES>>>(mnode0, dnode0, W_edge, b_edge, out, 512, 0);

    // KQ = EE @ Wqk + bqk -> g_KQ   (Q GEMM folded away)
    gemm_k<1, 1, 2, true, false, false, 256, 512>
        <<<dim3(64, 8), 256, GEMM_SMEM_BYTES>>>(nullptr, nullptr, nullptr, nullptr, nullptr, 0, 0);

    // attention -> g_WN
    attn_kernel<<<NB / 8, 256>>>(mrel0, mnode1, drel0, dnode1);

    // out[:, 256:] = WN @ Wv + bv
    gemm_k<3, 0, 0, true, false, false, 512, 256>
        <<<dim3(64, 4), 256, GEMM_SMEM_BYTES>>>(nullptr, nullptr, Wv, bv, out, 512, 256);
}